// round 1
// baseline (speedup 1.0000x reference)
#include <cuda_runtime.h>
#include <cstdint>

#define SEQ   8192
#define EMB   256
#define HID   512
#define G4    2048   // 4*HID

// ---------------- scratch (static device arrays; no allocation) -------------
__device__ float g_Xg[(size_t)SEQ * G4];            // 64 MB precomputed input gates
__device__ __align__(16) float g_hbuf[2 * HID];     // ping-pong hidden state
__device__ unsigned g_ctr;                          // monotonic barrier counter

// ---------------- init: reset barrier counter each launch -------------------
__global__ void init_kernel() {
    if (threadIdx.x == 0) g_ctr = 0u;
}

// ---------------- GEMM: Xg[t][r] = emb[x[t]] . W_ih[r] + b_ih[r] + b_hh[r] --
#define TT 32
#define TR 64
#define KC 64

__global__ void __launch_bounds__(256) gemm_kernel(
    const int* __restrict__ x, const float* __restrict__ emb,
    const float* __restrict__ W_ih, const float* __restrict__ b_ih,
    const float* __restrict__ b_hh)
{
    __shared__ float As[TT][KC + 1];   // [t][k], padded
    __shared__ float Bs[KC][TR];       // [k][r]

    const int t0 = blockIdx.x * TT;
    const int r0 = blockIdx.y * TR;
    const int tid = threadIdx.x;
    const int tx = tid & 15;    // r-quad index (r = r0 + tx*4 + q)
    const int ty = tid >> 4;    // t index (t = t0 + ty, t0 + ty + 16)

    float acc[2][4];
    #pragma unroll
    for (int i = 0; i < 2; i++)
        #pragma unroll
        for (int q = 0; q < 4; q++) acc[i][q] = 0.f;

    for (int kc = 0; kc < EMB; kc += KC) {
        // load A tile: 32 rows x 64 k  (512 float4 tasks)
        #pragma unroll
        for (int i = 0; i < 2; i++) {
            int task = tid * 2 + i;        // 0..511
            int t    = task >> 4;          // 16 float4 per row
            int kq   = task & 15;
            int row  = x[t0 + t];
            float4 v = *reinterpret_cast<const float4*>(
                emb + (size_t)row * EMB + kc + kq * 4);
            As[t][kq * 4 + 0] = v.x;
            As[t][kq * 4 + 1] = v.y;
            As[t][kq * 4 + 2] = v.z;
            As[t][kq * 4 + 3] = v.w;
        }
        // load B tile transposed: Bs[k][r], 64 r x 64 k (1024 float4 tasks)
        #pragma unroll
        for (int i = 0; i < 4; i++) {
            int task = tid * 4 + i;        // 0..1023
            int r    = task >> 4;          // 0..63
            int kq   = task & 15;
            float4 v = *reinterpret_cast<const float4*>(
                W_ih + (size_t)(r0 + r) * EMB + kc + kq * 4);
            Bs[kq * 4 + 0][r] = v.x;
            Bs[kq * 4 + 1][r] = v.y;
            Bs[kq * 4 + 2][r] = v.z;
            Bs[kq * 4 + 3][r] = v.w;
        }
        __syncthreads();

        #pragma unroll 8
        for (int k = 0; k < KC; k++) {
            float a0 = As[ty][k];
            float a1 = As[ty + 16][k];
            float4 b = *reinterpret_cast<const float4*>(&Bs[k][tx * 4]);
            acc[0][0] += a0 * b.x;  acc[0][1] += a0 * b.y;
            acc[0][2] += a0 * b.z;  acc[0][3] += a0 * b.w;
            acc[1][0] += a1 * b.x;  acc[1][1] += a1 * b.y;
            acc[1][2] += a1 * b.z;  acc[1][3] += a1 * b.w;
        }
        __syncthreads();
    }

    // epilogue: add biases, write Xg
    const int rbase = r0 + tx * 4;
    float4 bias;
    bias.x = b_ih[rbase + 0] + b_hh[rbase + 0];
    bias.y = b_ih[rbase + 1] + b_hh[rbase + 1];
    bias.z = b_ih[rbase + 2] + b_hh[rbase + 2];
    bias.w = b_ih[rbase + 3] + b_hh[rbase + 3];
    #pragma unroll
    for (int i = 0; i < 2; i++) {
        int t = t0 + ty + i * 16;
        float4 o;
        o.x = acc[i][0] + bias.x;
        o.y = acc[i][1] + bias.y;
        o.z = acc[i][2] + bias.z;
        o.w = acc[i][3] + bias.w;
        *reinterpret_cast<float4*>(g_Xg + (size_t)t * G4 + rbase) = o;
    }
}

// ---------------- recurrent LSTM: persistent, grid-synced -------------------
#define NCTA 64
#define NWARP 8     // warps per CTA; NCTA*NWARP == HID (one unit per warp)

__device__ __forceinline__ float sigmoid_f(float x) {
    return __fdividef(1.f, 1.f + __expf(-x));
}
__device__ __forceinline__ float tanh_f(float x) {
    // (e^{2x}-1)/(e^{2x}+1); saturates correctly for |x| large
    float e = __expf(2.f * x);
    return 1.f - __fdividef(2.f, e + 1.f);
}

__global__ void __launch_bounds__(256, 1) lstm_kernel(
    const float* __restrict__ W_hh, const float* __restrict__ h0,
    const float* __restrict__ c0, float* __restrict__ out)
{
    const int warp = threadIdx.x >> 5;
    const int lane = threadIdx.x & 31;
    const int j = blockIdx.x * NWARP + warp;    // hidden unit 0..511

    // --- preload 4 gate rows of W_hh, 16 columns per lane, into registers ---
    float w[4][16];
    #pragma unroll
    for (int g = 0; g < 4; g++) {
        const float4* p = reinterpret_cast<const float4*>(
            W_hh + (size_t)(g * HID + j) * HID + lane * 16);
        #pragma unroll
        for (int q = 0; q < 4; q++) {
            float4 v = p[q];
            w[g][q * 4 + 0] = v.x; w[g][q * 4 + 1] = v.y;
            w[g][q * 4 + 2] = v.z; w[g][q * 4 + 3] = v.w;
        }
    }

    float c = c0[j];

    // seed h buffer 0 with h0
    if (lane == 0) g_hbuf[j] = h0[j];

    // prefetch Xg for t=0
    const float* xp0 = g_Xg + j;
    float xg0 = xp0[0], xg1 = xp0[512], xg2 = xp0[1024], xg3 = xp0[1536];

    // --- initial barrier: all h0 slices visible to everyone ---
    __syncthreads();
    if (threadIdx.x == 0) {
        __threadfence();
        atomicAdd(&g_ctr, 1u);
        volatile unsigned* vc = &g_ctr;
        while (*vc < (unsigned)NCTA) { }
        __threadfence();
    }
    __syncthreads();

    for (int t = 0; t < SEQ; t++) {
        const float* hb = g_hbuf + (t & 1) * HID;

        // load h (bypass L1 — written by other CTAs)
        float hv[16];
        #pragma unroll
        for (int q = 0; q < 4; q++) {
            float4 v = __ldcv(reinterpret_cast<const float4*>(hb + lane * 16 + q * 4));
            hv[q * 4 + 0] = v.x; hv[q * 4 + 1] = v.y;
            hv[q * 4 + 2] = v.z; hv[q * 4 + 3] = v.w;
        }

        // prefetch next step's Xg (independent of h; hides DRAM latency)
        int tn = (t + 1 < SEQ) ? (t + 1) : t;
        const float* xpn = g_Xg + (size_t)tn * G4 + j;
        float nx0 = xpn[0], nx1 = xpn[512], nx2 = xpn[1024], nx3 = xpn[1536];

        // matvec slice: 4 gate rows x 16 columns per lane
        float a0 = 0.f, a1 = 0.f, a2 = 0.f, a3 = 0.f;
        #pragma unroll
        for (int k = 0; k < 16; k++) {
            a0 += w[0][k] * hv[k];
            a1 += w[1][k] * hv[k];
            a2 += w[2][k] * hv[k];
            a3 += w[3][k] * hv[k];
        }
        // butterfly reduce across 32 lanes (all lanes end with full sums)
        #pragma unroll
        for (int s = 16; s > 0; s >>= 1) {
            a0 += __shfl_xor_sync(0xffffffffu, a0, s);
            a1 += __shfl_xor_sync(0xffffffffu, a1, s);
            a2 += __shfl_xor_sync(0xffffffffu, a2, s);
            a3 += __shfl_xor_sync(0xffffffffu, a3, s);
        }

        float gi = a0 + xg0;
        float gf = a1 + xg1;
        float gg = a2 + xg2;
        float go = a3 + xg3;

        float si = sigmoid_f(gi);
        float sf = sigmoid_f(gf);
        float tg = tanh_f(gg);
        float so = sigmoid_f(go);
        c = sf * c + si * tg;
        float h = so * tanh_f(c);

        xg0 = nx0; xg1 = nx1; xg2 = nx2; xg3 = nx3;

        if (t == SEQ - 1) {
            if (lane == 0) out[j] = h;
        } else {
            if (lane == 0) g_hbuf[((t + 1) & 1) * HID + j] = h;
            __syncthreads();
            if (threadIdx.x == 0) {
                __threadfence();
                atomicAdd(&g_ctr, 1u);
                unsigned target = (unsigned)(t + 2) * NCTA;
                volatile unsigned* vc = &g_ctr;
                while (*vc < target) { }
                __threadfence();
            }
            __syncthreads();
        }
    }
}

// ---------------- launch -----------------------------------------------------
extern "C" void kernel_launch(void* const* d_in, const int* in_sizes, int n_in,
                              void* d_out, int out_size)
{
    const int*   x    = (const int*)  d_in[0];
    const float* emb  = (const float*)d_in[1];
    const float* W_ih = (const float*)d_in[2];
    const float* W_hh = (const float*)d_in[3];
    const float* b_ih = (const float*)d_in[4];
    const float* b_hh = (const float*)d_in[5];
    const float* h0   = (const float*)d_in[6];
    const float* c0   = (const float*)d_in[7];
    float* out = (float*)d_out;

    init_kernel<<<1, 32>>>();
    dim3 g(SEQ / TT, G4 / TR);
    gemm_kernel<<<g, 256>>>(x, emb, W_ih, b_ih, b_hh);
    lstm_kernel<<<NCTA, 256>>>(W_hh, h0, c0, out);
}

// round 3
// speedup vs baseline: 2.8834x; 2.8834x over previous
#include <cuda_runtime.h>
#include <cstdint>

#define SEQ   8192
#define EMB   256
#define HID   512
#define G4    2048   // 4*HID

// ---------------- scratch (static device arrays; no allocation) -------------
__device__ float g_Xg[(size_t)SEQ * G4];             // 64 MB precomputed input gates
__device__ __align__(16) float2 g_hpair[2][HID];     // (value, tag) pairs, 2 rotating slots

// ---------------- init: seed slot0 with (h0, tag=0), stamp slot1 ------------
__global__ void init_kernel(const float* __restrict__ h0) {
    int i = blockIdx.x * blockDim.x + threadIdx.x;
    if (i < HID) {
        g_hpair[0][i] = make_float2(h0[i], 0.0f);
        g_hpair[1][i] = make_float2(0.0f, -1.0f);   // never matches any expected tag
    }
}

// ---------------- GEMM: Xg[t][r] = emb[x[t]] . W_ih[r] + b_ih[r] + b_hh[r] --
#define TT 32
#define TR 64
#define KC 64

__global__ void __launch_bounds__(256) gemm_kernel(
    const int* __restrict__ x, const float* __restrict__ emb,
    const float* __restrict__ W_ih, const float* __restrict__ b_ih,
    const float* __restrict__ b_hh)
{
    __shared__ float As[TT][KC + 1];   // [t][k], padded
    __shared__ float Bs[KC][TR];       // [k][r]

    const int t0 = blockIdx.x * TT;
    const int r0 = blockIdx.y * TR;
    const int tid = threadIdx.x;
    const int tx = tid & 15;    // r-quad index (r = r0 + tx*4 + q)
    const int ty = tid >> 4;    // t index (t = t0 + ty, t0 + ty + 16)

    float acc[2][4];
    #pragma unroll
    for (int i = 0; i < 2; i++)
        #pragma unroll
        for (int q = 0; q < 4; q++) acc[i][q] = 0.f;

    for (int kc = 0; kc < EMB; kc += KC) {
        #pragma unroll
        for (int i = 0; i < 2; i++) {
            int task = tid * 2 + i;        // 0..511
            int t    = task >> 4;          // 16 float4 per row
            int kq   = task & 15;
            int row  = x[t0 + t];
            float4 v = *reinterpret_cast<const float4*>(
                emb + (size_t)row * EMB + kc + kq * 4);
            As[t][kq * 4 + 0] = v.x;
            As[t][kq * 4 + 1] = v.y;
            As[t][kq * 4 + 2] = v.z;
            As[t][kq * 4 + 3] = v.w;
        }
        #pragma unroll
        for (int i = 0; i < 4; i++) {
            int task = tid * 4 + i;        // 0..1023
            int r    = task >> 4;          // 0..63
            int kq   = task & 15;
            float4 v = *reinterpret_cast<const float4*>(
                W_ih + (size_t)(r0 + r) * EMB + kc + kq * 4);
            Bs[kq * 4 + 0][r] = v.x;
            Bs[kq * 4 + 1][r] = v.y;
            Bs[kq * 4 + 2][r] = v.z;
            Bs[kq * 4 + 3][r] = v.w;
        }
        __syncthreads();

        #pragma unroll 8
        for (int k = 0; k < KC; k++) {
            float a0 = As[ty][k];
            float a1 = As[ty + 16][k];
            float4 b = *reinterpret_cast<const float4*>(&Bs[k][tx * 4]);
            acc[0][0] += a0 * b.x;  acc[0][1] += a0 * b.y;
            acc[0][2] += a0 * b.z;  acc[0][3] += a0 * b.w;
            acc[1][0] += a1 * b.x;  acc[1][1] += a1 * b.y;
            acc[1][2] += a1 * b.z;  acc[1][3] += a1 * b.w;
        }
        __syncthreads();
    }

    const int rbase = r0 + tx * 4;
    float4 bias;
    bias.x = b_ih[rbase + 0] + b_hh[rbase + 0];
    bias.y = b_ih[rbase + 1] + b_hh[rbase + 1];
    bias.z = b_ih[rbase + 2] + b_hh[rbase + 2];
    bias.w = b_ih[rbase + 3] + b_hh[rbase + 3];
    #pragma unroll
    for (int i = 0; i < 2; i++) {
        int t = t0 + ty + i * 16;
        float4 o;
        o.x = acc[i][0] + bias.x;
        o.y = acc[i][1] + bias.y;
        o.z = acc[i][2] + bias.z;
        o.w = acc[i][3] + bias.w;
        *reinterpret_cast<float4*>(g_Xg + (size_t)t * G4 + rbase) = o;
    }
}

// ---------------- recurrent LSTM: persistent, dataflow-synced ----------------
#define NCTA   128
#define NWARP  4      // warps per CTA; NCTA*NWARP == HID (one unit per warp)
#define NTHR   (NWARP * 32)

__device__ __forceinline__ float sigmoid_f(float x) {
    return __fdividef(1.f, 1.f + __expf(-x));
}
__device__ __forceinline__ float tanh_f(float x) {
    float e = __expf(2.f * x);
    return 1.f - __fdividef(2.f, e + 1.f);
}

__global__ void __launch_bounds__(NTHR, 1) lstm_kernel(
    const float* __restrict__ W_hh, const float* __restrict__ c0,
    float* __restrict__ out)
{
    const int tid  = threadIdx.x;
    const int warp = tid >> 5;
    const int lane = tid & 31;
    const int j = blockIdx.x * NWARP + warp;     // hidden unit 0..511

    __shared__ __align__(16) float hsm[HID];

    // --- preload 4 gate rows of W_hh into registers.
    // lane l owns k in { q*128 + l*4 + e : q=0..3, e=0..3 }  (matches hsm LDS layout)
    float w[4][16];
    #pragma unroll
    for (int g = 0; g < 4; g++) {
        const float* row = W_hh + (size_t)(g * HID + j) * HID;
        #pragma unroll
        for (int q = 0; q < 4; q++) {
            float4 v = *reinterpret_cast<const float4*>(row + q * 128 + lane * 4);
            w[g][q * 4 + 0] = v.x; w[g][q * 4 + 1] = v.y;
            w[g][q * 4 + 2] = v.z; w[g][q * 4 + 3] = v.w;
        }
    }

    float c = c0[j];

    // prefetch Xg for t=0 (broadcast per warp)
    float xg0 = g_Xg[j +    0];
    float xg1 = g_Xg[j +  512];
    float xg2 = g_Xg[j + 1024];
    float xg3 = g_Xg[j + 1536];

    for (int t = 0; t < SEQ; t++) {
        // ---- fused poll + load of h slot (value,tag pairs); CTA-wide agree ----
        const float4* src = reinterpret_cast<const float4*>(g_hpair[t & 1]);
        const int exp_bits = __float_as_int((float)t);
        float4 pa, pb;
        int ok;
        do {
            pa = __ldcv(src + tid * 2 + 0);   // pairs 4*tid, 4*tid+1
            pb = __ldcv(src + tid * 2 + 1);   // pairs 4*tid+2, 4*tid+3
            ok = (__float_as_int(pa.y) == exp_bits) &
                 (__float_as_int(pa.w) == exp_bits) &
                 (__float_as_int(pb.y) == exp_bits) &
                 (__float_as_int(pb.w) == exp_bits);
        } while (!__syncthreads_and(ok));

        // stage values to smem (one STS.128 per thread)
        *reinterpret_cast<float4*>(&hsm[tid * 4]) =
            make_float4(pa.x, pa.z, pb.x, pb.z);
        __syncthreads();

        // prefetch next step's Xg (independent of h)
        int tn = (t + 1 < SEQ) ? (t + 1) : t;
        const float* xpn = g_Xg + (size_t)tn * G4 + j;
        float nx0 = xpn[0], nx1 = xpn[512], nx2 = xpn[1024], nx3 = xpn[1536];

        // matvec slice: 4 gate rows x 16 k per lane
        float a0 = 0.f, a1 = 0.f, a2 = 0.f, a3 = 0.f;
        #pragma unroll
        for (int q = 0; q < 4; q++) {
            float4 hq = *reinterpret_cast<const float4*>(&hsm[q * 128 + lane * 4]);
            float hv[4] = {hq.x, hq.y, hq.z, hq.w};
            #pragma unroll
            for (int e = 0; e < 4; e++) {
                a0 += w[0][q * 4 + e] * hv[e];
                a1 += w[1][q * 4 + e] * hv[e];
                a2 += w[2][q * 4 + e] * hv[e];
                a3 += w[3][q * 4 + e] * hv[e];
            }
        }
        #pragma unroll
        for (int s = 16; s > 0; s >>= 1) {
            a0 += __shfl_xor_sync(0xffffffffu, a0, s);
            a1 += __shfl_xor_sync(0xffffffffu, a1, s);
            a2 += __shfl_xor_sync(0xffffffffu, a2, s);
            a3 += __shfl_xor_sync(0xffffffffu, a3, s);
        }

        float si = sigmoid_f(a0 + xg0);
        float sf = sigmoid_f(a1 + xg1);
        float tg = tanh_f   (a2 + xg2);
        float so = sigmoid_f(a3 + xg3);
        c = sf * c + si * tg;
        float h = so * tanh_f(c);

        xg0 = nx0; xg1 = nx1; xg2 = nx2; xg3 = nx3;

        if (t == SEQ - 1) {
            if (lane == 0) out[j] = h;
        } else if (lane == 0) {
            // single aligned 8B store: value+tag become visible atomically
            __stcg(&g_hpair[(t + 1) & 1][j], make_float2(h, (float)(t + 1)));
        }
    }
}

// ---------------- launch -----------------------------------------------------
extern "C" void kernel_launch(void* const* d_in, const int* in_sizes, int n_in,
                              void* d_out, int out_size)
{
    const int*   x    = (const int*)  d_in[0];
    const float* emb  = (const float*)d_in[1];
    const float* W_ih = (const float*)d_in[2];
    const float* W_hh = (const float*)d_in[3];
    const float* b_ih = (const float*)d_in[4];
    const float* b_hh = (const float*)d_in[5];
    const float* h0   = (const float*)d_in[6];
    const float* c0   = (const float*)d_in[7];
    float* out = (float*)d_out;

    init_kernel<<<2, 256>>>(h0);
    dim3 g(SEQ / TT, G4 / TR);
    gemm_kernel<<<g, 256>>>(x, emb, W_ih, b_ih, b_hh);
    lstm_kernel<<<NCTA, NTHR>>>(W_hh, c0, out);
}